// round 6
// baseline (speedup 1.0000x reference)
#include <cuda_runtime.h>
#include <cuda_bf16.h>
#include <math.h>
#include <stdint.h>

#define B_  8
#define C_  256
#define H_  64
#define W_  64
#define HW  (H_*W_)
#define PLANE ((size_t)C_*HW)
#define NCHUNK 16
#define CHUNK  16
#define TILE_H 8
#define HALO_N 660
#define ASTRIDE 40
#define BSTRIDE 136

// per-buffer smem layout (bytes)
#define SM_AH   0
#define SM_AL   10240
#define SM_BH   20480
#define SM_BL   29184
#define SM_BUF  37888
#define GEMM_SMEM (2*SM_BUF)

// ------------------------- scratch (static device memory) -------------------
__device__ float g_fe  [B_*C_*HW];
__device__ float g_agg [B_*C_*HW];
__device__ float g_enh [B_*C_*HW];
__device__ float g_b1  [C_];
__device__ float g_b2  [C_];
__device__ float g_pooled[B_*2*C_];
__device__ float g_gate[B_*C_];
__device__ float g_part[NCHUNK*B_*10*HW];
__device__ float g_normp[B_*HW];
__device__ float g_wts9[9*B_*HW];
__device__ __nv_bfloat16 g_W1hi[C_*C_];
__device__ __nv_bfloat16 g_W1lo[C_*C_];
__device__ __nv_bfloat16 g_W2hi[C_*2*C_];
__device__ __nv_bfloat16 g_W2lo[C_*2*C_];

// ------------------------- PTX helpers --------------------------------------
__device__ __forceinline__ uint32_t smem_u32(const void* p) {
    uint32_t a;
    asm("{ .reg .u64 t; cvta.to.shared.u64 t, %1; cvt.u32.u64 %0, t; }" : "=r"(a) : "l"(p));
    return a;
}
#define LDSM4(r0,r1,r2,r3,addr) \
    asm volatile("ldmatrix.sync.aligned.m8n8.x4.shared.b16 {%0,%1,%2,%3}, [%4];" \
                 : "=r"(r0),"=r"(r1),"=r"(r2),"=r"(r3) : "r"(addr))
#define LDSM4T(r0,r1,r2,r3,addr) \
    asm volatile("ldmatrix.sync.aligned.m8n8.x4.trans.shared.b16 {%0,%1,%2,%3}, [%4];" \
                 : "=r"(r0),"=r"(r1),"=r"(r2),"=r"(r3) : "r"(addr))
#define MMA_BF16(d,a,b) \
    asm volatile("mma.sync.aligned.m16n8k16.row.col.f32.bf16.bf16.f32 " \
                 "{%0,%1,%2,%3},{%4,%5,%6,%7},{%8,%9},{%0,%1,%2,%3};" \
                 : "+f"((d)[0]),"+f"((d)[1]),"+f"((d)[2]),"+f"((d)[3]) \
                 : "r"((a)[0]),"r"((a)[1]),"r"((a)[2]),"r"((a)[3]), \
                   "r"((b)[0]),"r"((b)[1]))

__device__ __forceinline__ uint32_t pack_bf16x2(__nv_bfloat16 a, __nv_bfloat16 b) {
    return (uint32_t)__bfloat16_as_ushort(a) | ((uint32_t)__bfloat16_as_ushort(b) << 16);
}

// ------------------------- BN fold + bf16 split (both convs) -----------------
__global__ void fold_split_kernel(const float* __restrict__ W1, const float* __restrict__ bc1,
                                  const float* __restrict__ g1, const float* __restrict__ be1,
                                  const float* __restrict__ m1, const float* __restrict__ v1,
                                  const float* __restrict__ W2, const float* __restrict__ bc2,
                                  const float* __restrict__ g2, const float* __restrict__ be2,
                                  const float* __restrict__ m2, const float* __restrict__ v2,
                                  __nv_bfloat16* __restrict__ W1hi, __nv_bfloat16* __restrict__ W1lo,
                                  float* __restrict__ b1o,
                                  __nv_bfloat16* __restrict__ W2hi, __nv_bfloat16* __restrict__ W2lo,
                                  float* __restrict__ b2o)
{
    int o = blockIdx.x;
    const float* W = blockIdx.y ? W2 : W1;
    const float* bc = blockIdx.y ? bc2 : bc1;
    const float* ga = blockIdx.y ? g2 : g1;
    const float* be = blockIdx.y ? be2 : be1;
    const float* mn = blockIdx.y ? m2 : m1;
    const float* va = blockIdx.y ? v2 : v1;
    __nv_bfloat16* Whi = blockIdx.y ? W2hi : W1hi;
    __nv_bfloat16* Wlo = blockIdx.y ? W2lo : W1lo;
    float* bo = blockIdx.y ? b2o : b1o;
    int Kin = blockIdx.y ? 2 * C_ : C_;

    float inv = ga[o] / sqrtf(va[o] + 1e-5f);
    for (int i = threadIdx.x; i < Kin; i += blockDim.x) {
        float w = W[o * Kin + i] * inv;
        __nv_bfloat16 hb = __float2bfloat16(w);
        Whi[o * Kin + i] = hb;
        Wlo[o * Kin + i] = __float2bfloat16(w - __bfloat162float(hb));
    }
    if (threadIdx.x == 0)
        bo[o] = bc[o] * inv + be[o] - mn[o] * inv;
}

// ---------------- HMMA bf16x3 GEMM, double-buffered + reg prefetch -----------
__global__ __launch_bounds__(256)
void gemm_mma_kernel(const __nv_bfloat16* __restrict__ Whi,
                     const __nv_bfloat16* __restrict__ Wlo,
                     const float* __restrict__ X0,
                     const float* __restrict__ X1,
                     const float* __restrict__ bias,
                     float* __restrict__ out, int Kw)
{
    extern __shared__ char dsm[];
    const int tid = threadIdx.x, lane = tid & 31, wid = tid >> 5;
    const int mw = wid & 3, nw = wid >> 2;
    const int p0 = blockIdx.x * 128, m0 = blockIdx.y * 128, b = blockIdx.z;
    const int nK = Kw / 32;
    const uint32_t sbase = smem_u32(dsm);

    float acc[2][8][4];
#pragma unroll
    for (int i = 0; i < 2; i++)
#pragma unroll
        for (int j = 0; j < 8; j++)
#pragma unroll
            for (int q = 0; q < 4; q++) acc[i][j][q] = 0.f;

    // A-stage thread mapping (2 chunks): r = row, c = k offset
    const int ar0 = tid >> 2, ac0 = (tid & 3) * 8;
    // B-stage thread mapping (4 chunks)
    const uint32_t aoff = (uint32_t)(((mw * 32 + (lane & 15)) * ASTRIDE
                                      + (lane >> 4) * 8) * 2);
    const uint32_t boff = (uint32_t)(((((lane & 7) | (((lane >> 3) & 1) << 3)) * BSTRIDE)
                                      + nw * 64 + (lane >> 4) * 8) * 2);

    uint4 pah[2], pal[2];
    float4 pb[4];

    auto loadTile = [&](int k0) {
#pragma unroll
        for (int i = 0; i < 2; i++) {
            int r = ar0 + i * 64;
            size_t go = (size_t)(m0 + r) * Kw + k0 + ac0;
            pah[i] = *(const uint4*)(Whi + go);
            pal[i] = *(const uint4*)(Wlo + go);
        }
#pragma unroll
        for (int j = 0; j < 4; j++) {
            int idx = tid + j * 256;
            int k = idx >> 5, n4 = (idx & 31) * 4;
            int kg = k0 + k;
            const float* src = (kg < C_) ? X0 + ((size_t)b * C_ + kg) * HW
                                         : X1 + ((size_t)b * C_ + kg - C_) * HW;
            pb[j] = *(const float4*)(src + p0 + n4);
        }
    };
    auto commitTile = [&](int s) {
        char* base = dsm + s * SM_BUF;
        __nv_bfloat16* Ah = (__nv_bfloat16*)(base + SM_AH);
        __nv_bfloat16* Al = (__nv_bfloat16*)(base + SM_AL);
        __nv_bfloat16* Bh = (__nv_bfloat16*)(base + SM_BH);
        __nv_bfloat16* Bl = (__nv_bfloat16*)(base + SM_BL);
#pragma unroll
        for (int i = 0; i < 2; i++) {
            int r = ar0 + i * 64;
            *(uint4*)&Ah[r * ASTRIDE + ac0] = pah[i];
            *(uint4*)&Al[r * ASTRIDE + ac0] = pal[i];
        }
#pragma unroll
        for (int j = 0; j < 4; j++) {
            int idx = tid + j * 256;
            int k = idx >> 5, n4 = (idx & 31) * 4;
            float4 v = pb[j];
            __nv_bfloat16 hx = __float2bfloat16(v.x);
            __nv_bfloat16 hy = __float2bfloat16(v.y);
            __nv_bfloat16 hz = __float2bfloat16(v.z);
            __nv_bfloat16 hw = __float2bfloat16(v.w);
            *(uint2*)&Bh[k * BSTRIDE + n4] =
                make_uint2(pack_bf16x2(hx, hy), pack_bf16x2(hz, hw));
            *(uint2*)&Bl[k * BSTRIDE + n4] = make_uint2(
                pack_bf16x2(__float2bfloat16(v.x - __bfloat162float(hx)),
                            __float2bfloat16(v.y - __bfloat162float(hy))),
                pack_bf16x2(__float2bfloat16(v.z - __bfloat162float(hz)),
                            __float2bfloat16(v.w - __bfloat162float(hw))));
        }
    };

    loadTile(0);
    commitTile(0);
    __syncthreads();

    for (int t = 0; t < nK; t++) {
        const int s = t & 1;
        if (t + 1 < nK) loadTile((t + 1) * 32);

        const uint32_t base = sbase + s * SM_BUF;
        const uint32_t aAh = base + SM_AH, aAl = base + SM_AL;
        const uint32_t aBh = base + SM_BH, aBl = base + SM_BL;

#pragma unroll
        for (int ks = 0; ks < 2; ks++) {
            uint32_t ah[2][4], al[2][4];
#pragma unroll
            for (int mf = 0; mf < 2; mf++) {
                uint32_t o = aoff + (uint32_t)(mf * 16 * ASTRIDE * 2 + ks * 32);
                LDSM4(ah[mf][0], ah[mf][1], ah[mf][2], ah[mf][3], aAh + o);
                LDSM4(al[mf][0], al[mf][1], al[mf][2], al[mf][3], aAl + o);
            }
            uint32_t bf[8][2];
#pragma unroll
            for (int np = 0; np < 4; np++) {
                uint32_t o = boff + (uint32_t)(ks * 16 * BSTRIDE * 2 + np * 32);
                LDSM4T(bf[2*np][0], bf[2*np][1], bf[2*np+1][0], bf[2*np+1][1], aBh + o);
            }
#pragma unroll
            for (int mf = 0; mf < 2; mf++)
#pragma unroll
                for (int nf = 0; nf < 8; nf++) {
                    MMA_BF16(acc[mf][nf], ah[mf], bf[nf]);
                    MMA_BF16(acc[mf][nf], al[mf], bf[nf]);
                }
#pragma unroll
            for (int np = 0; np < 4; np++) {
                uint32_t o = boff + (uint32_t)(ks * 16 * BSTRIDE * 2 + np * 32);
                LDSM4T(bf[2*np][0], bf[2*np][1], bf[2*np+1][0], bf[2*np+1][1], aBl + o);
            }
#pragma unroll
            for (int mf = 0; mf < 2; mf++)
#pragma unroll
                for (int nf = 0; nf < 8; nf++)
                    MMA_BF16(acc[mf][nf], ah[mf], bf[nf]);
        }

        if (t + 1 < nK) {
            commitTile((t + 1) & 1);
            __syncthreads();
        }
    }

    // ---- epilogue: bias + relu
    const int rr = lane >> 2, cc2 = (lane & 3) * 2;
#pragma unroll
    for (int mf = 0; mf < 2; mf++) {
        int row = m0 + mw * 32 + mf * 16 + rr;
        float bs0 = bias[row], bs1 = bias[row + 8];
        float* d0 = out + ((size_t)b * C_ + row) * HW + p0 + nw * 64 + cc2;
        float* d1 = d0 + 8 * HW;
#pragma unroll
        for (int nf = 0; nf < 8; nf++) {
            float2 v0, v1;
            v0.x = fmaxf(acc[mf][nf][0] + bs0, 0.f);
            v0.y = fmaxf(acc[mf][nf][1] + bs0, 0.f);
            v1.x = fmaxf(acc[mf][nf][2] + bs1, 0.f);
            v1.y = fmaxf(acc[mf][nf][3] + bs1, 0.f);
            *(float2*)(d0 + nf * 8) = v0;
            *(float2*)(d1 + nf * 8) = v1;
        }
    }
}

// ---------------- sim partials ------------------------------------------------
__global__ __launch_bounds__(128)
void sim_part_kernel(const float* __restrict__ fe, float* __restrict__ part)
{
    const int h0 = blockIdx.x * TILE_H;
    const int b  = blockIdx.y;
    const int ch = blockIdx.z;
    const int c0 = ch * CHUNK;
    const int tid = threadIdx.x;
    const int lr = tid >> 4;
    const int base = (tid & 15) * 4;

    __shared__ float tile[HALO_N];

    float sacc[9][4];
    float nrm[4];
#pragma unroll
    for (int k = 0; k < 9; k++)
#pragma unroll
        for (int t = 0; t < 4; t++) sacc[k][t] = 0.f;
#pragma unroll
    for (int t = 0; t < 4; t++) nrm[t] = 0.f;

    const float* src = fe + ((size_t)b * C_ + c0) * HW;
    float pre[6];
#pragma unroll
    for (int l = 0; l < 6; l++) {
        int idx = tid + l * 128;
        float v = 0.f;
        if (idx < HALO_N) {
            int r = idx / 66, cc = idx - r * 66;
            int gh = h0 - 1 + r, gw = cc - 1;
            if ((unsigned)gh < (unsigned)H_ && (unsigned)gw < (unsigned)W_)
                v = src[gh * W_ + gw];
        }
        pre[l] = v;
    }

    for (int c = 0; c < CHUNK; c++) {
#pragma unroll
        for (int l = 0; l < 6; l++) {
            int idx = tid + l * 128;
            if (idx < HALO_N) tile[idx] = pre[l];
        }
        __syncthreads();
        if (c + 1 < CHUNK) {
            const float* nsrc = src + (size_t)(c + 1) * HW;
#pragma unroll
            for (int l = 0; l < 6; l++) {
                int idx = tid + l * 128;
                float v = 0.f;
                if (idx < HALO_N) {
                    int r = idx / 66, cc = idx - r * 66;
                    int gh = h0 - 1 + r, gw = cc - 1;
                    if ((unsigned)gh < (unsigned)H_ && (unsigned)gw < (unsigned)W_)
                        v = nsrc[gh * W_ + gw];
                }
                pre[l] = v;
            }
        }
        float v0[6], v1[6], v2[6];
#pragma unroll
        for (int m = 0; m < 6; m++) {
            v0[m] = tile[(lr + 0) * 66 + base + m];
            v1[m] = tile[(lr + 1) * 66 + base + m];
            v2[m] = tile[(lr + 2) * 66 + base + m];
        }
#pragma unroll
        for (int t = 0; t < 4; t++) {
            float cv = v1[t + 1];
            nrm[t] += cv * cv;
#pragma unroll
            for (int j = 0; j < 3; j++) {
                sacc[0 + j][t] += cv * v0[t + j];
                sacc[3 + j][t] += cv * v1[t + j];
                sacc[6 + j][t] += cv * v2[t + j];
            }
        }
        __syncthreads();
    }

    const size_t pbase = ((size_t)(ch * B_ + b)) * 10 * HW + (size_t)(h0 + lr) * W_ + base;
#pragma unroll
    for (int k = 0; k < 9; k++)
        *(float4*)(part + pbase + (size_t)k * HW) =
            make_float4(sacc[k][0], sacc[k][1], sacc[k][2], sacc[k][3]);
    *(float4*)(part + pbase + (size_t)9 * HW) =
        make_float4(nrm[0], nrm[1], nrm[2], nrm[3]);
}

__global__ void norm_sum_kernel(const float* __restrict__ part, float* __restrict__ normp)
{
    int p = blockIdx.x * 256 + threadIdx.x;
    int b = p >> 12, hw = p & (HW - 1);
    float s = 0.f;
#pragma unroll
    for (int ch = 0; ch < NCHUNK; ch++)
        s += part[((size_t)(ch * B_ + b) * 10 + 9) * HW + hw];
    normp[p] = s;
}

__global__ void weights_kernel(const float* __restrict__ part,
                               const float* __restrict__ normp,
                               float* __restrict__ wts)
{
    int p  = blockIdx.x * 256 + threadIdx.x;
    int b  = p >> 12, hw = p & (HW - 1);
    int h  = hw >> 6,  w = hw & 63;

    float sim[9];
#pragma unroll
    for (int k = 0; k < 9; k++) sim[k] = 0.f;
#pragma unroll
    for (int ch = 0; ch < NCHUNK; ch++) {
        const float* pp = part + (size_t)(ch * B_ + b) * 10 * HW + hw;
#pragma unroll
        for (int k = 0; k < 9; k++) sim[k] += pp[(size_t)k * HW];
    }
    float nc = sqrtf(normp[p]);

    float s[9], m = -1e30f;
#pragma unroll
    for (int i = 0; i < 3; i++)
#pragma unroll
        for (int j = 0; j < 3; j++) {
            int nh = h + i - 1, nw = w + j - 1;
            float nb = 0.f;
            if ((unsigned)nh < (unsigned)H_ && (unsigned)nw < (unsigned)W_)
                nb = normp[b * HW + nh * W_ + nw];
            int k = i * 3 + j;
            s[k] = sim[k] / (nc * sqrtf(nb) + 1e-7f);
            m = fmaxf(m, s[k]);
        }
    float sum = 0.f;
#pragma unroll
    for (int k = 0; k < 9; k++) { s[k] = expf(s[k] - m); sum += s[k]; }
    float rinv = 1.f / sum;
#pragma unroll
    for (int k = 0; k < 9; k++)
        wts[(size_t)k * (B_ * HW) + p] = s[k] * rinv;
}

__global__ __launch_bounds__(128)
void agg_kernel(const float* __restrict__ x, const float* __restrict__ wts,
                float* __restrict__ agg)
{
    const int h0 = blockIdx.x * TILE_H;
    const int b  = blockIdx.y;
    const int c0 = blockIdx.z * CHUNK;
    const int tid = threadIdx.x;
    const int lr = tid >> 4;
    const int base = (tid & 15) * 4;

    __shared__ float tile[HALO_N];

    float w9[9][4];
    {
        size_t pidx = (size_t)b * HW + (size_t)(h0 + lr) * W_ + base;
#pragma unroll
        for (int k = 0; k < 9; k++) {
            float4 v = *(const float4*)(wts + (size_t)k * (B_ * HW) + pidx);
            w9[k][0] = v.x; w9[k][1] = v.y; w9[k][2] = v.z; w9[k][3] = v.w;
        }
    }

    const float* src = x + ((size_t)b * C_ + c0) * HW;
    float pre[6];
#pragma unroll
    for (int l = 0; l < 6; l++) {
        int idx = tid + l * 128;
        float v = 0.f;
        if (idx < HALO_N) {
            int r = idx / 66, cc = idx - r * 66;
            int gh = h0 - 1 + r, gw = cc - 1;
            if ((unsigned)gh < (unsigned)H_ && (unsigned)gw < (unsigned)W_)
                v = src[gh * W_ + gw];
        }
        pre[l] = v;
    }

    for (int c = 0; c < CHUNK; c++) {
#pragma unroll
        for (int l = 0; l < 6; l++) {
            int idx = tid + l * 128;
            if (idx < HALO_N) tile[idx] = pre[l];
        }
        __syncthreads();
        if (c + 1 < CHUNK) {
            const float* nsrc = src + (size_t)(c + 1) * HW;
#pragma unroll
            for (int l = 0; l < 6; l++) {
                int idx = tid + l * 128;
                float v = 0.f;
                if (idx < HALO_N) {
                    int r = idx / 66, cc = idx - r * 66;
                    int gh = h0 - 1 + r, gw = cc - 1;
                    if ((unsigned)gh < (unsigned)H_ && (unsigned)gw < (unsigned)W_)
                        v = nsrc[gh * W_ + gw];
                }
                pre[l] = v;
            }
        }
        float v0[6], v1[6], v2[6];
#pragma unroll
        for (int m = 0; m < 6; m++) {
            v0[m] = tile[(lr + 0) * 66 + base + m];
            v1[m] = tile[(lr + 1) * 66 + base + m];
            v2[m] = tile[(lr + 2) * 66 + base + m];
        }
        float a[4];
#pragma unroll
        for (int t = 0; t < 4; t++) {
            float acc = 0.f;
#pragma unroll
            for (int j = 0; j < 3; j++) {
                acc += w9[0 + j][t] * v0[t + j];
                acc += w9[3 + j][t] * v1[t + j];
                acc += w9[6 + j][t] * v2[t + j];
            }
            a[t] = acc;
        }
        float* dst = agg + ((size_t)b * C_ + c0 + c) * HW + (size_t)(h0 + lr) * W_ + base;
        *(float4*)dst = make_float4(a[0], a[1], a[2], a[3]);
        __syncthreads();
    }
}

// ------------------------- pooling / gating / residual ----------------------
__global__ void pool_kernel(const float* __restrict__ x, const float* __restrict__ enh,
                            float* __restrict__ pooled)
{
    const int b  = blockIdx.y;
    const int cc = blockIdx.x;
    const float* src = (cc < C_) ? (x   + ((size_t)b * C_ + cc)      * HW)
                                 : (enh + ((size_t)b * C_ + cc - C_) * HW);
    float s = 0.f;
    for (int i = threadIdx.x; i < HW; i += 128) s += src[i];
#pragma unroll
    for (int off = 16; off > 0; off >>= 1)
        s += __shfl_down_sync(0xffffffffu, s, off);
    __shared__ float red[4];
    if ((threadIdx.x & 31) == 0) red[threadIdx.x >> 5] = s;
    __syncthreads();
    if (threadIdx.x == 0)
        pooled[b * (2 * C_) + cc] = (red[0] + red[1] + red[2] + red[3]) * (1.f / (float)HW);
}

__global__ __launch_bounds__(256)
void gate_kernel(const float* __restrict__ pooled,
                 const float* __restrict__ wg1, const float* __restrict__ bg1,
                 const float* __restrict__ wg2, const float* __restrict__ bg2,
                 float* __restrict__ gate)
{
    const int b = blockIdx.x;
    __shared__ float sp[512];
    __shared__ float sh[64];
    const int tid = threadIdx.x;
    for (int i = tid; i < 512; i += 256) sp[i] = pooled[b * 512 + i];
    __syncthreads();
    if (tid < 64) {
        float a = bg1[tid];
        for (int i = 0; i < 512; i++) a += wg1[tid * 512 + i] * sp[i];
        sh[tid] = fmaxf(a, 0.f);
    }
    __syncthreads();
    float a = bg2[tid];
#pragma unroll
    for (int j = 0; j < 64; j++) a += wg2[tid * 64 + j] * sh[j];
    gate[b * C_ + tid] = 1.f / (1.f + expf(-a));
}

__global__ void final_kernel(const float* __restrict__ x, const float* __restrict__ enh,
                             const float* __restrict__ gate, float* __restrict__ out)
{
    size_t i4 = (size_t)blockIdx.x * 256 + threadIdx.x;
    size_t bc = i4 / (HW / 4);
    float wv = gate[bc];
    float4 xv = ((const float4*)x)[i4];
    float4 ev = ((const float4*)enh)[i4];
    float4 o;
    o.x = xv.x + wv * ev.x;  o.y = xv.y + wv * ev.y;
    o.z = xv.z + wv * ev.z;  o.w = xv.w + wv * ev.w;
    ((float4*)out)[i4] = o;
}

// ------------------------- launcher ------------------------------------------
extern "C" void kernel_launch(void* const* d_in, const int* in_sizes, int n_in,
                              void* d_out, int out_size)
{
    const float* x        = (const float*)d_in[0];
    const float* w_embed  = (const float*)d_in[1];
    const float* b_embed  = (const float*)d_in[2];
    const float* bn1_g    = (const float*)d_in[3];
    const float* bn1_b    = (const float*)d_in[4];
    const float* bn1_m    = (const float*)d_in[5];
    const float* bn1_v    = (const float*)d_in[6];
    const float* w_enh    = (const float*)d_in[7];
    const float* b_enh    = (const float*)d_in[8];
    const float* bn2_g    = (const float*)d_in[9];
    const float* bn2_b    = (const float*)d_in[10];
    const float* bn2_m    = (const float*)d_in[11];
    const float* bn2_v    = (const float*)d_in[12];
    const float* w_g1     = (const float*)d_in[13];
    const float* b_g1     = (const float*)d_in[14];
    const float* w_g2     = (const float*)d_in[15];
    const float* b_g2     = (const float*)d_in[16];
    float* out = (float*)d_out;

    float *fe, *agg, *enh, *b1, *b2, *pooled, *gate, *part, *normp, *wts;
    __nv_bfloat16 *W1hi, *W1lo, *W2hi, *W2lo;
    cudaGetSymbolAddress((void**)&fe,   g_fe);
    cudaGetSymbolAddress((void**)&agg,  g_agg);
    cudaGetSymbolAddress((void**)&enh,  g_enh);
    cudaGetSymbolAddress((void**)&b1,   g_b1);
    cudaGetSymbolAddress((void**)&b2,   g_b2);
    cudaGetSymbolAddress((void**)&pooled, g_pooled);
    cudaGetSymbolAddress((void**)&gate, g_gate);
    cudaGetSymbolAddress((void**)&part, g_part);
    cudaGetSymbolAddress((void**)&normp, g_normp);
    cudaGetSymbolAddress((void**)&wts,  g_wts9);
    cudaGetSymbolAddress((void**)&W1hi, g_W1hi);
    cudaGetSymbolAddress((void**)&W1lo, g_W1lo);
    cudaGetSymbolAddress((void**)&W2hi, g_W2hi);
    cudaGetSymbolAddress((void**)&W2lo, g_W2lo);

    cudaFuncSetAttribute(gemm_mma_kernel, cudaFuncAttributeMaxDynamicSharedMemorySize, GEMM_SMEM);

    // 1) BN fold + bf16 hi/lo split (both convs, one launch)
    dim3 fgrid(C_, 2);
    fold_split_kernel<<<fgrid, 256>>>(w_embed, b_embed, bn1_g, bn1_b, bn1_m, bn1_v,
                                      w_enh, b_enh, bn2_g, bn2_b, bn2_m, bn2_v,
                                      W1hi, W1lo, b1, W2hi, W2lo, b2);

    // 2) fe = relu(bn1(W_embed @ x))
    dim3 ggrid(HW / 128, C_ / 128, B_);
    gemm_mma_kernel<<<ggrid, 256, GEMM_SMEM>>>(W1hi, W1lo, x, x, b1, fe, C_);

    // 3) similarity -> softmax weights -> aggregation
    dim3 sgrid(H_ / TILE_H, B_, NCHUNK);
    sim_part_kernel<<<sgrid, 128>>>(fe, part);
    norm_sum_kernel<<<(B_ * HW) / 256, 256>>>(part, normp);
    weights_kernel<<<(B_ * HW) / 256, 256>>>(part, normp, wts);
    agg_kernel<<<sgrid, 128>>>(x, wts, agg);

    // 4) enhanced = relu(bn2(W_enh @ [x; agg]))
    gemm_mma_kernel<<<ggrid, 256, GEMM_SMEM>>>(W2hi, W2lo, x, agg, b2, enh, 2 * C_);

    // 5) pooled mean of [x; enhanced]
    dim3 pgrid(2 * C_, B_);
    pool_kernel<<<pgrid, 128>>>(x, enh, pooled);

    // 6) SE gating
    gate_kernel<<<B_, 256>>>(pooled, w_g1, b_g1, w_g2, b_g2, gate);

    // 7) out = x + weights * enhanced
    final_kernel<<<(B_ * C_ * HW / 4) / 256, 256>>>(x, enh, gate, out);
}

// round 7
// speedup vs baseline: 1.1587x; 1.1587x over previous
#include <cuda_runtime.h>
#include <cuda_fp16.h>
#include <math.h>
#include <stdint.h>

#define B_  8
#define C_  256
#define H_  64
#define W_  64
#define HW  (H_*W_)
#define PLANE ((size_t)C_*HW)
#define NCHUNK 16
#define CHUNK  16
#define TILE_H 8
#define HALO_N 660
#define ASTRIDE 40
#define BSTRIDE 136

// per-buffer smem layout (bytes): A hi, A lo (128x40 half), B (32x136 half)
#define SM_AH   0
#define SM_AL   10240
#define SM_BH   20480
#define SM_BUF  29184
#define GEMM_SMEM (2*SM_BUF)

// ------------------------- scratch (static device memory) -------------------
__device__ float g_fe  [B_*C_*HW];
__device__ float g_agg [B_*C_*HW];
__device__ float g_enh [B_*C_*HW];
__device__ float g_b1  [C_];
__device__ float g_b2  [C_];
__device__ float g_pooled[B_*2*C_];
__device__ float g_gate[B_*C_];
__device__ float g_part[NCHUNK*B_*10*HW];
__device__ float g_normp[B_*HW];
__device__ float g_wts9[9*B_*HW];
__device__ __half g_W1hi[C_*C_];
__device__ __half g_W1lo[C_*C_];
__device__ __half g_W2hi[C_*2*C_];
__device__ __half g_W2lo[C_*2*C_];

// ------------------------- PTX helpers --------------------------------------
__device__ __forceinline__ uint32_t smem_u32(const void* p) {
    uint32_t a;
    asm("{ .reg .u64 t; cvta.to.shared.u64 t, %1; cvt.u32.u64 %0, t; }" : "=r"(a) : "l"(p));
    return a;
}
#define LDSM4(r0,r1,r2,r3,addr) \
    asm volatile("ldmatrix.sync.aligned.m8n8.x4.shared.b16 {%0,%1,%2,%3}, [%4];" \
                 : "=r"(r0),"=r"(r1),"=r"(r2),"=r"(r3) : "r"(addr))
#define LDSM4T(r0,r1,r2,r3,addr) \
    asm volatile("ldmatrix.sync.aligned.m8n8.x4.trans.shared.b16 {%0,%1,%2,%3}, [%4];" \
                 : "=r"(r0),"=r"(r1),"=r"(r2),"=r"(r3) : "r"(addr))
#define MMA_F16(d,a,b) \
    asm volatile("mma.sync.aligned.m16n8k16.row.col.f32.f16.f16.f32 " \
                 "{%0,%1,%2,%3},{%4,%5,%6,%7},{%8,%9},{%0,%1,%2,%3};" \
                 : "+f"((d)[0]),"+f"((d)[1]),"+f"((d)[2]),"+f"((d)[3]) \
                 : "r"((a)[0]),"r"((a)[1]),"r"((a)[2]),"r"((a)[3]), \
                   "r"((b)[0]),"r"((b)[1]))

// ------------------------- BN fold + fp16 hi/lo split (both convs) -----------
__global__ void fold_split_kernel(const float* __restrict__ W1, const float* __restrict__ bc1,
                                  const float* __restrict__ g1, const float* __restrict__ be1,
                                  const float* __restrict__ m1, const float* __restrict__ v1,
                                  const float* __restrict__ W2, const float* __restrict__ bc2,
                                  const float* __restrict__ g2, const float* __restrict__ be2,
                                  const float* __restrict__ m2, const float* __restrict__ v2,
                                  __half* __restrict__ W1hi, __half* __restrict__ W1lo,
                                  float* __restrict__ b1o,
                                  __half* __restrict__ W2hi, __half* __restrict__ W2lo,
                                  float* __restrict__ b2o)
{
    int o = blockIdx.x;
    const float* W = blockIdx.y ? W2 : W1;
    const float* bc = blockIdx.y ? bc2 : bc1;
    const float* ga = blockIdx.y ? g2 : g1;
    const float* be = blockIdx.y ? be2 : be1;
    const float* mn = blockIdx.y ? m2 : m1;
    const float* va = blockIdx.y ? v2 : v1;
    __half* Whi = blockIdx.y ? W2hi : W1hi;
    __half* Wlo = blockIdx.y ? W2lo : W1lo;
    float* bo = blockIdx.y ? b2o : b1o;
    int Kin = blockIdx.y ? 2 * C_ : C_;

    float inv = ga[o] / sqrtf(va[o] + 1e-5f);
    for (int i = threadIdx.x; i < Kin; i += blockDim.x) {
        float w = W[o * Kin + i] * inv;
        __half hb = __float2half_rn(w);
        Whi[o * Kin + i] = hb;
        Wlo[o * Kin + i] = __float2half_rn(w - __half2float(hb));
    }
    if (threadIdx.x == 0)
        bo[o] = bc[o] * inv + be[o] - mn[o] * inv;
}

// ---------------- HMMA fp16 (Whi+Wlo)·X GEMM, double buffered ----------------
// A = W [M][K] fp16 hi/lo pre-split. B = activations f32 [K][N], rounded to
// single fp16 at staging. acc = Whi*X + Wlo*X  (2 MMAs per fragment pair).
__global__ __launch_bounds__(256)
void gemm_mma_kernel(const __half* __restrict__ Whi,
                     const __half* __restrict__ Wlo,
                     const float* __restrict__ X0,
                     const float* __restrict__ X1,
                     const float* __restrict__ bias,
                     float* __restrict__ out, int Kw)
{
    extern __shared__ char dsm[];
    const int tid = threadIdx.x, lane = tid & 31, wid = tid >> 5;
    const int mw = wid & 3, nw = wid >> 2;
    const int p0 = blockIdx.x * 128, m0 = blockIdx.y * 128, b = blockIdx.z;
    const int nK = Kw / 32;
    const uint32_t sbase = smem_u32(dsm);

    float acc[2][8][4];
#pragma unroll
    for (int i = 0; i < 2; i++)
#pragma unroll
        for (int j = 0; j < 8; j++)
#pragma unroll
            for (int q = 0; q < 4; q++) acc[i][j][q] = 0.f;

    const int ar0 = tid >> 2, ac0 = (tid & 3) * 8;
    const uint32_t aoff = (uint32_t)(((mw * 32 + (lane & 15)) * ASTRIDE
                                      + (lane >> 4) * 8) * 2);
    const uint32_t boff = (uint32_t)(((((lane & 7) | (((lane >> 3) & 1) << 3)) * BSTRIDE)
                                      + nw * 64 + (lane >> 4) * 8) * 2);

    uint4 pah[2], pal[2];
    float4 pb[4];

    auto loadTile = [&](int k0) {
#pragma unroll
        for (int i = 0; i < 2; i++) {
            int r = ar0 + i * 64;
            size_t go = (size_t)(m0 + r) * Kw + k0 + ac0;
            pah[i] = *(const uint4*)(Whi + go);
            pal[i] = *(const uint4*)(Wlo + go);
        }
#pragma unroll
        for (int j = 0; j < 4; j++) {
            int idx = tid + j * 256;
            int k = idx >> 5, n4 = (idx & 31) * 4;
            int kg = k0 + k;
            const float* src = (kg < C_) ? X0 + ((size_t)b * C_ + kg) * HW
                                         : X1 + ((size_t)b * C_ + kg - C_) * HW;
            pb[j] = *(const float4*)(src + p0 + n4);
        }
    };
    auto commitTile = [&](int s) {
        char* base = dsm + s * SM_BUF;
        __half* Ah = (__half*)(base + SM_AH);
        __half* Al = (__half*)(base + SM_AL);
        __half* Bh = (__half*)(base + SM_BH);
#pragma unroll
        for (int i = 0; i < 2; i++) {
            int r = ar0 + i * 64;
            *(uint4*)&Ah[r * ASTRIDE + ac0] = pah[i];
            *(uint4*)&Al[r * ASTRIDE + ac0] = pal[i];
        }
#pragma unroll
        for (int j = 0; j < 4; j++) {
            int idx = tid + j * 256;
            int k = idx >> 5, n4 = (idx & 31) * 4;
            float4 v = pb[j];
            __half2 h01 = __floats2half2_rn(v.x, v.y);
            __half2 h23 = __floats2half2_rn(v.z, v.w);
            *(uint2*)&Bh[k * BSTRIDE + n4] =
                make_uint2(*(uint32_t*)&h01, *(uint32_t*)&h23);
        }
    };

    loadTile(0);
    commitTile(0);
    __syncthreads();

    for (int t = 0; t < nK; t++) {
        const int s = t & 1;
        if (t + 1 < nK) loadTile((t + 1) * 32);

        const uint32_t base = sbase + s * SM_BUF;
        const uint32_t aAh = base + SM_AH, aAl = base + SM_AL;
        const uint32_t aBh = base + SM_BH;

#pragma unroll
        for (int ks = 0; ks < 2; ks++) {
            uint32_t ah[2][4], al[2][4];
#pragma unroll
            for (int mf = 0; mf < 2; mf++) {
                uint32_t o = aoff + (uint32_t)(mf * 16 * ASTRIDE * 2 + ks * 32);
                LDSM4(ah[mf][0], ah[mf][1], ah[mf][2], ah[mf][3], aAh + o);
                LDSM4(al[mf][0], al[mf][1], al[mf][2], al[mf][3], aAl + o);
            }
            uint32_t bf[8][2];
#pragma unroll
            for (int np = 0; np < 4; np++) {
                uint32_t o = boff + (uint32_t)(ks * 16 * BSTRIDE * 2 + np * 32);
                LDSM4T(bf[2*np][0], bf[2*np][1], bf[2*np+1][0], bf[2*np+1][1], aBh + o);
            }
#pragma unroll
            for (int mf = 0; mf < 2; mf++)
#pragma unroll
                for (int nf = 0; nf < 8; nf++) {
                    MMA_F16(acc[mf][nf], ah[mf], bf[nf]);
                    MMA_F16(acc[mf][nf], al[mf], bf[nf]);
                }
        }

        if (t + 1 < nK) {
            commitTile((t + 1) & 1);
            __syncthreads();
        }
    }

    const int rr = lane >> 2, cc2 = (lane & 3) * 2;
#pragma unroll
    for (int mf = 0; mf < 2; mf++) {
        int row = m0 + mw * 32 + mf * 16 + rr;
        float bs0 = bias[row], bs1 = bias[row + 8];
        float* d0 = out + ((size_t)b * C_ + row) * HW + p0 + nw * 64 + cc2;
        float* d1 = d0 + 8 * HW;
#pragma unroll
        for (int nf = 0; nf < 8; nf++) {
            float2 v0, v1;
            v0.x = fmaxf(acc[mf][nf][0] + bs0, 0.f);
            v0.y = fmaxf(acc[mf][nf][1] + bs0, 0.f);
            v1.x = fmaxf(acc[mf][nf][2] + bs1, 0.f);
            v1.y = fmaxf(acc[mf][nf][3] + bs1, 0.f);
            *(float2*)(d0 + nf * 8) = v0;
            *(float2*)(d1 + nf * 8) = v1;
        }
    }
}

// ---------------- sim partials: 2 channels per barrier pair ------------------
__global__ __launch_bounds__(128)
void sim_part_kernel(const float* __restrict__ fe, float* __restrict__ part)
{
    const int h0 = blockIdx.x * TILE_H;
    const int b  = blockIdx.y;
    const int ch = blockIdx.z;
    const int c0 = ch * CHUNK;
    const int tid = threadIdx.x;
    const int lr = tid >> 4;
    const int base = (tid & 15) * 4;

    __shared__ float tile[2][HALO_N];

    float sacc[9][4];
    float nrm[4];
#pragma unroll
    for (int k = 0; k < 9; k++)
#pragma unroll
        for (int t = 0; t < 4; t++) sacc[k][t] = 0.f;
#pragma unroll
    for (int t = 0; t < 4; t++) nrm[t] = 0.f;

    // halo index precompute
    int hidx[6], hok[6];
#pragma unroll
    for (int l = 0; l < 6; l++) {
        int idx = tid + l * 128;
        int r = idx / 66, cc = idx - r * 66;
        int gh = h0 - 1 + r, gw = cc - 1;
        hok[l] = (idx < HALO_N) &&
                 ((unsigned)gh < (unsigned)H_) && ((unsigned)gw < (unsigned)W_);
        hidx[l] = gh * W_ + gw;
    }

    const float* src = fe + ((size_t)b * C_ + c0) * HW;
    float pre[2][6];
#pragma unroll
    for (int u = 0; u < 2; u++)
#pragma unroll
        for (int l = 0; l < 6; l++)
            pre[u][l] = hok[l] ? src[(size_t)u * HW + hidx[l]] : 0.f;

    for (int c = 0; c < CHUNK; c += 2) {
#pragma unroll
        for (int u = 0; u < 2; u++)
#pragma unroll
            for (int l = 0; l < 6; l++) {
                int idx = tid + l * 128;
                if (idx < HALO_N) tile[u][idx] = pre[u][l];
            }
        __syncthreads();
        if (c + 2 < CHUNK) {
            const float* nsrc = src + (size_t)(c + 2) * HW;
#pragma unroll
            for (int u = 0; u < 2; u++)
#pragma unroll
                for (int l = 0; l < 6; l++)
                    pre[u][l] = hok[l] ? nsrc[(size_t)u * HW + hidx[l]] : 0.f;
        }
#pragma unroll
        for (int u = 0; u < 2; u++) {
            float v0[6], v1[6], v2[6];
#pragma unroll
            for (int m = 0; m < 6; m++) {
                v0[m] = tile[u][(lr + 0) * 66 + base + m];
                v1[m] = tile[u][(lr + 1) * 66 + base + m];
                v2[m] = tile[u][(lr + 2) * 66 + base + m];
            }
#pragma unroll
            for (int t = 0; t < 4; t++) {
                float cv = v1[t + 1];
                nrm[t] += cv * cv;
#pragma unroll
                for (int j = 0; j < 3; j++) {
                    sacc[0 + j][t] += cv * v0[t + j];
                    sacc[3 + j][t] += cv * v1[t + j];
                    sacc[6 + j][t] += cv * v2[t + j];
                }
            }
        }
        __syncthreads();
    }

    const size_t pbase = ((size_t)(ch * B_ + b)) * 10 * HW + (size_t)(h0 + lr) * W_ + base;
#pragma unroll
    for (int k = 0; k < 9; k++)
        *(float4*)(part + pbase + (size_t)k * HW) =
            make_float4(sacc[k][0], sacc[k][1], sacc[k][2], sacc[k][3]);
    *(float4*)(part + pbase + (size_t)9 * HW) =
        make_float4(nrm[0], nrm[1], nrm[2], nrm[3]);
}

__global__ void norm_sum_kernel(const float* __restrict__ part, float* __restrict__ normp)
{
    int p = blockIdx.x * 256 + threadIdx.x;
    int b = p >> 12, hw = p & (HW - 1);
    float s = 0.f;
#pragma unroll
    for (int ch = 0; ch < NCHUNK; ch++)
        s += part[((size_t)(ch * B_ + b) * 10 + 9) * HW + hw];
    normp[p] = s;
}

__global__ void weights_kernel(const float* __restrict__ part,
                               const float* __restrict__ normp,
                               float* __restrict__ wts)
{
    int p  = blockIdx.x * 256 + threadIdx.x;
    int b  = p >> 12, hw = p & (HW - 1);
    int h  = hw >> 6,  w = hw & 63;

    float sim[9];
#pragma unroll
    for (int k = 0; k < 9; k++) sim[k] = 0.f;
#pragma unroll
    for (int ch = 0; ch < NCHUNK; ch++) {
        const float* pp = part + (size_t)(ch * B_ + b) * 10 * HW + hw;
#pragma unroll
        for (int k = 0; k < 9; k++) sim[k] += pp[(size_t)k * HW];
    }
    float nc = sqrtf(normp[p]);

    float s[9], m = -1e30f;
#pragma unroll
    for (int i = 0; i < 3; i++)
#pragma unroll
        for (int j = 0; j < 3; j++) {
            int nh = h + i - 1, nw = w + j - 1;
            float nb = 0.f;
            if ((unsigned)nh < (unsigned)H_ && (unsigned)nw < (unsigned)W_)
                nb = normp[b * HW + nh * W_ + nw];
            int k = i * 3 + j;
            s[k] = sim[k] / (nc * sqrtf(nb) + 1e-7f);
            m = fmaxf(m, s[k]);
        }
    float sum = 0.f;
#pragma unroll
    for (int k = 0; k < 9; k++) { s[k] = expf(s[k] - m); sum += s[k]; }
    float rinv = 1.f / sum;
#pragma unroll
    for (int k = 0; k < 9; k++)
        wts[(size_t)k * (B_ * HW) + p] = s[k] * rinv;
}

// ---------------- aggregation: 2 channels per barrier pair -------------------
__global__ __launch_bounds__(128)
void agg_kernel(const float* __restrict__ x, const float* __restrict__ wts,
                float* __restrict__ agg)
{
    const int h0 = blockIdx.x * TILE_H;
    const int b  = blockIdx.y;
    const int c0 = blockIdx.z * CHUNK;
    const int tid = threadIdx.x;
    const int lr = tid >> 4;
    const int base = (tid & 15) * 4;

    __shared__ float tile[2][HALO_N];

    float w9[9][4];
    {
        size_t pidx = (size_t)b * HW + (size_t)(h0 + lr) * W_ + base;
#pragma unroll
        for (int k = 0; k < 9; k++) {
            float4 v = *(const float4*)(wts + (size_t)k * (B_ * HW) + pidx);
            w9[k][0] = v.x; w9[k][1] = v.y; w9[k][2] = v.z; w9[k][3] = v.w;
        }
    }

    int hidx[6], hok[6];
#pragma unroll
    for (int l = 0; l < 6; l++) {
        int idx = tid + l * 128;
        int r = idx / 66, cc = idx - r * 66;
        int gh = h0 - 1 + r, gw = cc - 1;
        hok[l] = (idx < HALO_N) &&
                 ((unsigned)gh < (unsigned)H_) && ((unsigned)gw < (unsigned)W_);
        hidx[l] = gh * W_ + gw;
    }

    const float* src = x + ((size_t)b * C_ + c0) * HW;
    float pre[2][6];
#pragma unroll
    for (int u = 0; u < 2; u++)
#pragma unroll
        for (int l = 0; l < 6; l++)
            pre[u][l] = hok[l] ? src[(size_t)u * HW + hidx[l]] : 0.f;

    for (int c = 0; c < CHUNK; c += 2) {
#pragma unroll
        for (int u = 0; u < 2; u++)
#pragma unroll
            for (int l = 0; l < 6; l++) {
                int idx = tid + l * 128;
                if (idx < HALO_N) tile[u][idx] = pre[u][l];
            }
        __syncthreads();
        if (c + 2 < CHUNK) {
            const float* nsrc = src + (size_t)(c + 2) * HW;
#pragma unroll
            for (int u = 0; u < 2; u++)
#pragma unroll
                for (int l = 0; l < 6; l++)
                    pre[u][l] = hok[l] ? nsrc[(size_t)u * HW + hidx[l]] : 0.f;
        }
#pragma unroll
        for (int u = 0; u < 2; u++) {
            float v0[6], v1[6], v2[6];
#pragma unroll
            for (int m = 0; m < 6; m++) {
                v0[m] = tile[u][(lr + 0) * 66 + base + m];
                v1[m] = tile[u][(lr + 1) * 66 + base + m];
                v2[m] = tile[u][(lr + 2) * 66 + base + m];
            }
            float a[4];
#pragma unroll
            for (int t = 0; t < 4; t++) {
                float acc = 0.f;
#pragma unroll
                for (int j = 0; j < 3; j++) {
                    acc += w9[0 + j][t] * v0[t + j];
                    acc += w9[3 + j][t] * v1[t + j];
                    acc += w9[6 + j][t] * v2[t + j];
                }
                a[t] = acc;
            }
            float* dst = agg + ((size_t)b * C_ + c0 + c + u) * HW
                         + (size_t)(h0 + lr) * W_ + base;
            *(float4*)dst = make_float4(a[0], a[1], a[2], a[3]);
        }
        __syncthreads();
    }
}

// ------------------------- pooling / gating / residual ----------------------
__global__ void pool_kernel(const float* __restrict__ x, const float* __restrict__ enh,
                            float* __restrict__ pooled)
{
    const int b  = blockIdx.y;
    const int cc = blockIdx.x;
    const float* src = (cc < C_) ? (x   + ((size_t)b * C_ + cc)      * HW)
                                 : (enh + ((size_t)b * C_ + cc - C_) * HW);
    float s = 0.f;
    for (int i = threadIdx.x; i < HW; i += 128) s += src[i];
#pragma unroll
    for (int off = 16; off > 0; off >>= 1)
        s += __shfl_down_sync(0xffffffffu, s, off);
    __shared__ float red[4];
    if ((threadIdx.x & 31) == 0) red[threadIdx.x >> 5] = s;
    __syncthreads();
    if (threadIdx.x == 0)
        pooled[b * (2 * C_) + cc] = (red[0] + red[1] + red[2] + red[3]) * (1.f / (float)HW);
}

__global__ __launch_bounds__(256)
void gate_kernel(const float* __restrict__ pooled,
                 const float* __restrict__ wg1, const float* __restrict__ bg1,
                 const float* __restrict__ wg2, const float* __restrict__ bg2,
                 float* __restrict__ gate)
{
    const int b = blockIdx.x;
    __shared__ float sp[512];
    __shared__ float sh[64];
    const int tid = threadIdx.x;
    for (int i = tid; i < 512; i += 256) sp[i] = pooled[b * 512 + i];
    __syncthreads();
    if (tid < 64) {
        float a = bg1[tid];
        for (int i = 0; i < 512; i++) a += wg1[tid * 512 + i] * sp[i];
        sh[tid] = fmaxf(a, 0.f);
    }
    __syncthreads();
    float a = bg2[tid];
#pragma unroll
    for (int j = 0; j < 64; j++) a += wg2[tid * 64 + j] * sh[j];
    gate[b * C_ + tid] = 1.f / (1.f + expf(-a));
}

__global__ void final_kernel(const float* __restrict__ x, const float* __restrict__ enh,
                             const float* __restrict__ gate, float* __restrict__ out)
{
    size_t i4 = (size_t)blockIdx.x * 256 + threadIdx.x;
    size_t bc = i4 / (HW / 4);
    float wv = gate[bc];
    float4 xv = ((const float4*)x)[i4];
    float4 ev = ((const float4*)enh)[i4];
    float4 o;
    o.x = xv.x + wv * ev.x;  o.y = xv.y + wv * ev.y;
    o.z = xv.z + wv * ev.z;  o.w = xv.w + wv * ev.w;
    ((float4*)out)[i4] = o;
}

// ------------------------- launcher ------------------------------------------
extern "C" void kernel_launch(void* const* d_in, const int* in_sizes, int n_in,
                              void* d_out, int out_size)
{
    const float* x        = (const float*)d_in[0];
    const float* w_embed  = (const float*)d_in[1];
    const float* b_embed  = (const float*)d_in[2];
    const float* bn1_g    = (const float*)d_in[3];
    const float* bn1_b    = (const float*)d_in[4];
    const float* bn1_m    = (const float*)d_in[5];
    const float* bn1_v    = (const float*)d_in[6];
    const float* w_enh    = (const float*)d_in[7];
    const float* b_enh    = (const float*)d_in[8];
    const float* bn2_g    = (const float*)d_in[9];
    const float* bn2_b    = (const float*)d_in[10];
    const float* bn2_m    = (const float*)d_in[11];
    const float* bn2_v    = (const float*)d_in[12];
    const float* w_g1     = (const float*)d_in[13];
    const float* b_g1     = (const float*)d_in[14];
    const float* w_g2     = (const float*)d_in[15];
    const float* b_g2     = (const float*)d_in[16];
    float* out = (float*)d_out;

    float *fe, *agg, *enh, *b1, *b2, *pooled, *gate, *part, *normp, *wts;
    __half *W1hi, *W1lo, *W2hi, *W2lo;
    cudaGetSymbolAddress((void**)&fe,   g_fe);
    cudaGetSymbolAddress((void**)&agg,  g_agg);
    cudaGetSymbolAddress((void**)&enh,  g_enh);
    cudaGetSymbolAddress((void**)&b1,   g_b1);
    cudaGetSymbolAddress((void**)&b2,   g_b2);
    cudaGetSymbolAddress((void**)&pooled, g_pooled);
    cudaGetSymbolAddress((void**)&gate, g_gate);
    cudaGetSymbolAddress((void**)&part, g_part);
    cudaGetSymbolAddress((void**)&normp, g_normp);
    cudaGetSymbolAddress((void**)&wts,  g_wts9);
    cudaGetSymbolAddress((void**)&W1hi, g_W1hi);
    cudaGetSymbolAddress((void**)&W1lo, g_W1lo);
    cudaGetSymbolAddress((void**)&W2hi, g_W2hi);
    cudaGetSymbolAddress((void**)&W2lo, g_W2lo);

    cudaFuncSetAttribute(gemm_mma_kernel, cudaFuncAttributeMaxDynamicSharedMemorySize, GEMM_SMEM);

    // 1) BN fold + fp16 hi/lo split (both convs, one launch)
    dim3 fgrid(C_, 2);
    fold_split_kernel<<<fgrid, 256>>>(w_embed, b_embed, bn1_g, bn1_b, bn1_m, bn1_v,
                                      w_enh, b_enh, bn2_g, bn2_b, bn2_m, bn2_v,
                                      W1hi, W1lo, b1, W2hi, W2lo, b2);

    // 2) fe = relu(bn1(W_embed @ x))
    dim3 ggrid(HW / 128, C_ / 128, B_);
    gemm_mma_kernel<<<ggrid, 256, GEMM_SMEM>>>(W1hi, W1lo, x, x, b1, fe, C_);

    // 3) similarity -> softmax weights -> aggregation
    dim3 sgrid(H_ / TILE_H, B_, NCHUNK);
    sim_part_kernel<<<sgrid, 128>>>(fe, part);
    norm_sum_kernel<<<(B_ * HW) / 256, 256>>>(part, normp);
    weights_kernel<<<(B_ * HW) / 256, 256>>>(part, normp, wts);
    agg_kernel<<<sgrid, 128>>>(x, wts, agg);

    // 4) enhanced = relu(bn2(W_enh @ [x; agg]))
    gemm_mma_kernel<<<ggrid, 256, GEMM_SMEM>>>(W2hi, W2lo, x, agg, b2, enh, 2 * C_);

    // 5) pooled mean of [x; enhanced]
    dim3 pgrid(2 * C_, B_);
    pool_kernel<<<pgrid, 128>>>(x, enh, pooled);

    // 6) SE gating
    gate_kernel<<<B_, 256>>>(pooled, w_g1, b_g1, w_g2, b_g2, gate);

    // 7) out = x + weights * enhanced
    final_kernel<<<(B_ * C_ * HW / 4) / 256, 256>>>(x, enh, gate, out);
}